// round 1
// baseline (speedup 1.0000x reference)
#include <cuda_runtime.h>
#include <math.h>

// Problem constants
#define BATCH   8
#define T       8192
#define IN_F    128
#define OUT_F   128
#define NSTATE  256
#define NC      64            // number of time chunks
#define CHUNK   128           // T / NC
#define MROWS   (BATCH * T)   // 65536
#define SCOLS   512           // 2*NSTATE (re | im)
#define KOUT    640           // 512 (states) + 128 (x for D term)

// -------- scratch (device globals; no cudaMalloc allowed) --------
__device__ float   g_S[(size_t)MROWS * SCOLS];        // Bu, then states (in place)
__device__ float   g_W[SCOLS * IN_F];                 // [gamma*B_re ; gamma*B_im]
__device__ float   g_Wout[OUT_F * KOUT];              // [C_re | -C_im | D] per output row
__device__ float   g_carry[BATCH * NC * NSTATE * 2];  // per-chunk carries -> prefix states
__device__ float2  g_lam[NSTATE];                     // Lambda (fp32)
__device__ double2 g_lamL[NSTATE];                    // Lambda^CHUNK (fp64)

// ======================= K1: prep weights / Lambda =======================
__global__ void prep_kernel(const float* __restrict__ nu_log,
                            const float* __restrict__ theta_log,
                            const float* __restrict__ gamma_log,
                            const float* __restrict__ B_re,
                            const float* __restrict__ B_im,
                            const float* __restrict__ C_re,
                            const float* __restrict__ C_im,
                            const float* __restrict__ D)
{
    int tid = threadIdx.x;   // 256 threads, 1 block
    if (tid < NSTATE) {
        int n = tid;
        double nu  = exp((double)nu_log[n]);
        double mod = exp(-nu);
        double th  = exp((double)theta_log[n]);
        g_lam[n] = make_float2((float)(mod * cos(th)), (float)(mod * sin(th)));
        double modL = exp(-(double)CHUNK * nu);
        double phL  = (double)CHUNK * th;
        g_lamL[n] = make_double2(modL * cos(phL), modL * sin(phL));
        float gam = expf(gamma_log[n]);
        for (int i = 0; i < IN_F; i++) {
            g_W[n * IN_F + i]            = gam * B_re[n * IN_F + i];
            g_W[(n + NSTATE) * IN_F + i] = gam * B_im[n * IN_F + i];
        }
    }
    // combined output weight: [C_re | -C_im | D], row-major [OUT_F, KOUT]
    for (int idx = tid; idx < OUT_F * KOUT; idx += blockDim.x) {
        int o = idx / KOUT, k = idx % KOUT;
        float v;
        if (k < 256)       v =  C_re[o * NSTATE + k];
        else if (k < 512)  v = -C_im[o * NSTATE + (k - 256)];
        else               v =  D[o * IN_F + (k - 512)];
        g_Wout[idx] = v;
    }
}

// ======================= K2: GEMM1  g_S = x @ W^T =======================
// M=65536, N=512, K=128. 128x128 block tile, 8x8 per thread, BK=16.
__global__ void gemm1_kernel(const float* __restrict__ A)
{
    const int K = IN_F;
    __shared__ float As[16][128];
    __shared__ float Bs[16][128];
    int tid = threadIdx.x;
    int tx = tid & 15, ty = tid >> 4;
    const float* Ablk = A   + (size_t)blockIdx.x * 128 * K;
    const float* Wblk = g_W + (size_t)blockIdx.y * 128 * K;
    float acc[8][8];
    #pragma unroll
    for (int i = 0; i < 8; i++)
        #pragma unroll
        for (int j = 0; j < 8; j++) acc[i][j] = 0.f;

    int r = tid >> 2;
    int c = (tid & 3) << 2;
    for (int k0 = 0; k0 < K; k0 += 16) {
        float4 a0 = *(const float4*)(Ablk + (size_t)r        * K + k0 + c);
        float4 a1 = *(const float4*)(Ablk + (size_t)(r + 64) * K + k0 + c);
        float4 b0 = *(const float4*)(Wblk + (size_t)r        * K + k0 + c);
        float4 b1 = *(const float4*)(Wblk + (size_t)(r + 64) * K + k0 + c);
        As[c+0][r] = a0.x; As[c+1][r] = a0.y; As[c+2][r] = a0.z; As[c+3][r] = a0.w;
        As[c+0][r+64] = a1.x; As[c+1][r+64] = a1.y; As[c+2][r+64] = a1.z; As[c+3][r+64] = a1.w;
        Bs[c+0][r] = b0.x; Bs[c+1][r] = b0.y; Bs[c+2][r] = b0.z; Bs[c+3][r] = b0.w;
        Bs[c+0][r+64] = b1.x; Bs[c+1][r+64] = b1.y; Bs[c+2][r+64] = b1.z; Bs[c+3][r+64] = b1.w;
        __syncthreads();
        #pragma unroll
        for (int k = 0; k < 16; k++) {
            float4 av0 = *(const float4*)&As[k][ty * 8];
            float4 av1 = *(const float4*)&As[k][ty * 8 + 4];
            float4 bv0 = *(const float4*)&Bs[k][tx * 8];
            float4 bv1 = *(const float4*)&Bs[k][tx * 8 + 4];
            float av[8] = {av0.x, av0.y, av0.z, av0.w, av1.x, av1.y, av1.z, av1.w};
            float bv[8] = {bv0.x, bv0.y, bv0.z, bv0.w, bv1.x, bv1.y, bv1.z, bv1.w};
            #pragma unroll
            for (int i = 0; i < 8; i++)
                #pragma unroll
                for (int j = 0; j < 8; j++)
                    acc[i][j] += av[i] * bv[j];
        }
        __syncthreads();
    }
    #pragma unroll
    for (int i = 0; i < 8; i++) {
        float* p = g_S + (size_t)(blockIdx.x * 128 + ty * 8 + i) * SCOLS
                       + blockIdx.y * 128 + tx * 8;
        *(float4*)(p)     = make_float4(acc[i][0], acc[i][1], acc[i][2], acc[i][3]);
        *(float4*)(p + 4) = make_float4(acc[i][4], acc[i][5], acc[i][6], acc[i][7]);
    }
}

// ======================= K3: per-chunk local carries =======================
__global__ void carry_kernel()
{
    int b = blockIdx.x >> 6;        // / NC
    int c = blockIdx.x & 63;        // % NC
    int n = threadIdx.x;            // 256
    float2 lam = g_lam[n];
    float sre = 0.f, sim = 0.f;
    const float* base = g_S + ((size_t)(b * T + c * CHUNK)) * SCOLS;
    #pragma unroll 4
    for (int j = 0; j < CHUNK; j++) {
        float bre = base[(size_t)j * SCOLS + n];
        float bim = base[(size_t)j * SCOLS + NSTATE + n];
        float nre = fmaf(lam.x, sre, fmaf(-lam.y, sim, bre));
        float nim = fmaf(lam.x, sim, fmaf( lam.y, sre, bim));
        sre = nre; sim = nim;
    }
    size_t idx = (((size_t)b * NC + c) * NSTATE + n) * 2;
    g_carry[idx]     = sre;
    g_carry[idx + 1] = sim;
}

// ========== K4: cross-chunk combine (fp64) -> g_carry holds end-of-chunk states ==========
__global__ void combine_kernel()
{
    int b = blockIdx.x;             // 8 blocks
    int n = threadIdx.x;            // 256
    double2 lL = g_lamL[n];
    double pre = 0.0, pim = 0.0;
    for (int c = 0; c < NC; c++) {
        size_t idx = (((size_t)b * NC + c) * NSTATE + n) * 2;
        double cre = (double)g_carry[idx];
        double cim = (double)g_carry[idx + 1];
        double nre = lL.x * pre - lL.y * pim + cre;
        double nim = lL.x * pim + lL.y * pre + cim;
        pre = nre; pim = nim;
        g_carry[idx]     = (float)pre;
        g_carry[idx + 1] = (float)pim;
    }
}

// ======================= K5: final scan (correct init), in-place =======================
__global__ void scan_final_kernel()
{
    int b = blockIdx.x >> 6;
    int c = blockIdx.x & 63;
    int n = threadIdx.x;
    float2 lam = g_lam[n];
    float sre = 0.f, sim = 0.f;
    if (c > 0) {
        size_t pidx = (((size_t)b * NC + (c - 1)) * NSTATE + n) * 2;
        sre = g_carry[pidx];
        sim = g_carry[pidx + 1];
    }
    float* base = g_S + ((size_t)(b * T + c * CHUNK)) * SCOLS;
    #pragma unroll 4
    for (int j = 0; j < CHUNK; j++) {
        float bre = base[(size_t)j * SCOLS + n];
        float bim = base[(size_t)j * SCOLS + NSTATE + n];
        float nre = fmaf(lam.x, sre, fmaf(-lam.y, sim, bre));
        float nim = fmaf(lam.x, sim, fmaf( lam.y, sre, bim));
        sre = nre; sim = nim;
        base[(size_t)j * SCOLS + n]          = nre;
        base[(size_t)j * SCOLS + NSTATE + n] = nim;
    }
}

// ====== K6: GEMM2  out = S @ [C_re|-C_im]^T + x @ D^T  (K=640 fused) ======
__global__ void gemm2_kernel(const float* __restrict__ X, float* __restrict__ Out)
{
    __shared__ float As[16][128];
    __shared__ float Bs[16][128];
    int tid = threadIdx.x;
    int tx = tid & 15, ty = tid >> 4;
    size_t m0 = (size_t)blockIdx.x * 128;
    float acc[8][8];
    #pragma unroll
    for (int i = 0; i < 8; i++)
        #pragma unroll
        for (int j = 0; j < 8; j++) acc[i][j] = 0.f;

    int r = tid >> 2;
    int c = (tid & 3) << 2;
    for (int k0 = 0; k0 < KOUT; k0 += 16) {
        float4 a0, a1;
        if (k0 < 512) {
            a0 = *(const float4*)(g_S + (m0 + r)      * (size_t)SCOLS + k0 + c);
            a1 = *(const float4*)(g_S + (m0 + r + 64) * (size_t)SCOLS + k0 + c);
        } else {
            a0 = *(const float4*)(X + (m0 + r)      * (size_t)IN_F + (k0 - 512) + c);
            a1 = *(const float4*)(X + (m0 + r + 64) * (size_t)IN_F + (k0 - 512) + c);
        }
        float4 b0 = *(const float4*)(g_Wout + (size_t)r        * KOUT + k0 + c);
        float4 b1 = *(const float4*)(g_Wout + (size_t)(r + 64) * KOUT + k0 + c);
        As[c+0][r] = a0.x; As[c+1][r] = a0.y; As[c+2][r] = a0.z; As[c+3][r] = a0.w;
        As[c+0][r+64] = a1.x; As[c+1][r+64] = a1.y; As[c+2][r+64] = a1.z; As[c+3][r+64] = a1.w;
        Bs[c+0][r] = b0.x; Bs[c+1][r] = b0.y; Bs[c+2][r] = b0.z; Bs[c+3][r] = b0.w;
        Bs[c+0][r+64] = b1.x; Bs[c+1][r+64] = b1.y; Bs[c+2][r+64] = b1.z; Bs[c+3][r+64] = b1.w;
        __syncthreads();
        #pragma unroll
        for (int k = 0; k < 16; k++) {
            float4 av0 = *(const float4*)&As[k][ty * 8];
            float4 av1 = *(const float4*)&As[k][ty * 8 + 4];
            float4 bv0 = *(const float4*)&Bs[k][tx * 8];
            float4 bv1 = *(const float4*)&Bs[k][tx * 8 + 4];
            float av[8] = {av0.x, av0.y, av0.z, av0.w, av1.x, av1.y, av1.z, av1.w};
            float bv[8] = {bv0.x, bv0.y, bv0.z, bv0.w, bv1.x, bv1.y, bv1.z, bv1.w};
            #pragma unroll
            for (int i = 0; i < 8; i++)
                #pragma unroll
                for (int j = 0; j < 8; j++)
                    acc[i][j] += av[i] * bv[j];
        }
        __syncthreads();
    }
    #pragma unroll
    for (int i = 0; i < 8; i++) {
        float* p = Out + (m0 + ty * 8 + i) * (size_t)OUT_F + tx * 8;
        *(float4*)(p)     = make_float4(acc[i][0], acc[i][1], acc[i][2], acc[i][3]);
        *(float4*)(p + 4) = make_float4(acc[i][4], acc[i][5], acc[i][6], acc[i][7]);
    }
}

// ======================= launch =======================
extern "C" void kernel_launch(void* const* d_in, const int* in_sizes, int n_in,
                              void* d_out, int out_size)
{
    const float* x         = (const float*)d_in[0];
    const float* nu_log    = (const float*)d_in[1];
    const float* theta_log = (const float*)d_in[2];
    const float* gamma_log = (const float*)d_in[3];
    const float* B_re      = (const float*)d_in[4];
    const float* B_im      = (const float*)d_in[5];
    const float* C_re      = (const float*)d_in[6];
    const float* C_im      = (const float*)d_in[7];
    const float* D         = (const float*)d_in[8];
    float* out = (float*)d_out;

    prep_kernel<<<1, 256>>>(nu_log, theta_log, gamma_log, B_re, B_im, C_re, C_im, D);
    gemm1_kernel<<<dim3(MROWS / 128, SCOLS / 128), 256>>>(x);
    carry_kernel<<<BATCH * NC, NSTATE>>>();
    combine_kernel<<<BATCH, NSTATE>>>();
    scan_final_kernel<<<BATCH * NC, NSTATE>>>();
    gemm2_kernel<<<MROWS / 128, 256>>>(x, out);
}

// round 3
// speedup vs baseline: 2.2629x; 2.2629x over previous
#include <cuda_runtime.h>
#include <cuda_bf16.h>
#include <math.h>
#include <stdint.h>

// ---------------- problem constants ----------------
#define BATCH   8
#define T       8192
#define IN_F    128
#define OUT_F   128
#define NSTATE  256
#define NC      64
#define CHUNK   128
#define MROWS   (BATCH * T)     // 65536
#define SCOLS   512             // 2*NSTATE (re | im)
#define KOUT    640             // 512 states + 128 x

// ---------------- scratch (device globals) ----------------
__device__ __align__(256) float         g_S[(size_t)MROWS * SCOLS];   // Bu (fp32)
__device__ __align__(256) __nv_bfloat16 g_Sh[(size_t)MROWS * SCOLS];  // states hi
__device__ __align__(256) __nv_bfloat16 g_Sl[(size_t)MROWS * SCOLS];  // states lo
__device__ __align__(256) __nv_bfloat16 g_xh[(size_t)MROWS * IN_F];
__device__ __align__(256) __nv_bfloat16 g_xl[(size_t)MROWS * IN_F];
__device__ __align__(256) __nv_bfloat16 g_W1h[SCOLS * IN_F];
__device__ __align__(256) __nv_bfloat16 g_W1l[SCOLS * IN_F];
__device__ __align__(256) __nv_bfloat16 g_Woh[OUT_F * KOUT];
__device__ __align__(256) __nv_bfloat16 g_Wol[OUT_F * KOUT];
__device__ float   g_carry[BATCH * NC * NSTATE * 2];
__device__ float2  g_lam[NSTATE];
__device__ double2 g_lamL[NSTATE];

// ---------------- PTX helpers (all plain-sm_100-legal) ----------------
__device__ __forceinline__ uint32_t smem_u32(const void* p) {
    uint32_t a;
    asm("{ .reg .u64 t; cvta.to.shared.u64 t, %1; cvt.u32.u64 %0, t; }" : "=r"(a) : "l"(p));
    return a;
}
__device__ __forceinline__ void cp16(uint32_t smem, const void* g) {
    asm volatile("cp.async.cg.shared.global [%0], [%1], 16;" :: "r"(smem), "l"(g));
}
#define CP_COMMIT() asm volatile("cp.async.commit_group;" ::: "memory")
template <int N>
__device__ __forceinline__ void cp_wait() {
    asm volatile("cp.async.wait_group %0;" :: "n"(N) : "memory");
}
__device__ __forceinline__ void ldsm4(uint32_t* r, uint32_t addr) {
    asm volatile("ldmatrix.sync.aligned.m8n8.x4.shared.b16 {%0,%1,%2,%3}, [%4];"
                 : "=r"(r[0]), "=r"(r[1]), "=r"(r[2]), "=r"(r[3]) : "r"(addr));
}
__device__ __forceinline__ void mma_bf16(float* c, const uint32_t* a, const uint32_t* b) {
    asm volatile("mma.sync.aligned.m16n8k16.row.col.f32.bf16.bf16.f32 "
                 "{%0,%1,%2,%3}, {%4,%5,%6,%7}, {%8,%9}, {%0,%1,%2,%3};"
                 : "+f"(c[0]), "+f"(c[1]), "+f"(c[2]), "+f"(c[3])
                 : "r"(a[0]), "r"(a[1]), "r"(a[2]), "r"(a[3]), "r"(b[0]), "r"(b[1]));
}

// ---------------- prep ----------------
__device__ __forceinline__ void split_bf16(float v, __nv_bfloat16& h, __nv_bfloat16& l) {
    h = __float2bfloat16(v);
    l = __float2bfloat16(v - __bfloat162float(h));
}

__global__ void prep_lambda_kernel(const float* __restrict__ nu_log,
                                   const float* __restrict__ theta_log) {
    int n = threadIdx.x;
    double nu  = exp((double)nu_log[n]);
    double th  = exp((double)theta_log[n]);
    double mod = exp(-nu);
    g_lam[n] = make_float2((float)(mod * cos(th)), (float)(mod * sin(th)));
    double modL = exp(-(double)CHUNK * nu);
    double phL  = (double)CHUNK * th;
    g_lamL[n] = make_double2(modL * cos(phL), modL * sin(phL));
}

__global__ void prep_w1_kernel(const float* __restrict__ gamma_log,
                               const float* __restrict__ B_re,
                               const float* __restrict__ B_im) {
    int idx = blockIdx.x * blockDim.x + threadIdx.x;
    if (idx >= SCOLS * IN_F) return;
    int n = idx / IN_F, i = idx % IN_F;
    float gam = expf(gamma_log[n & (NSTATE - 1)]);
    float v = gam * (n < NSTATE ? B_re[n * IN_F + i] : B_im[(n - NSTATE) * IN_F + i]);
    split_bf16(v, g_W1h[idx], g_W1l[idx]);
}

__global__ void prep_wout_kernel(const float* __restrict__ C_re,
                                 const float* __restrict__ C_im,
                                 const float* __restrict__ D) {
    int idx = blockIdx.x * blockDim.x + threadIdx.x;
    if (idx >= OUT_F * KOUT) return;
    int o = idx / KOUT, k = idx % KOUT;
    float v;
    if (k < 256)      v =  C_re[o * NSTATE + k];
    else if (k < 512) v = -C_im[o * NSTATE + (k - 256)];
    else              v =  D[o * IN_F + (k - 512)];
    split_bf16(v, g_Woh[idx], g_Wol[idx]);
}

__global__ void convert_x_kernel(const float* __restrict__ x) {
    size_t i = ((size_t)blockIdx.x * blockDim.x + threadIdx.x) * 4;
    float4 v = *(const float4*)(x + i);
    __nv_bfloat16 h0, l0, h1, l1, h2, l2, h3, l3;
    split_bf16(v.x, h0, l0); split_bf16(v.y, h1, l1);
    split_bf16(v.z, h2, l2); split_bf16(v.w, h3, l3);
    __nv_bfloat162* ph = (__nv_bfloat162*)(g_xh + i);
    __nv_bfloat162* pl = (__nv_bfloat162*)(g_xl + i);
    ph[0] = __nv_bfloat162(h0, h1); ph[1] = __nv_bfloat162(h2, h3);
    pl[0] = __nv_bfloat162(l0, l1); pl[1] = __nv_bfloat162(l2, l3);
}

// ---------------- MMA GEMM ----------------
// Block 128x128, 8 warps of 64x32, K-chunk 32, 2-stage cp.async double buffer.
// smem tile: 128 rows x 32 bf16 cols, row stride 80B (conflict-free ldmatrix).
#define ROW_B   80
#define TILE_B  (128 * ROW_B)          // 10240
#define STAGE_B (4 * TILE_B)           // Ah, Al, Bh, Bl
#define GSMEM   (2 * STAGE_B)          // 81920

__device__ __forceinline__ void load_tile(uint32_t sm, const __nv_bfloat16* __restrict__ g,
                                          size_t row0, int ld, int kb, int tid) {
    #pragma unroll
    for (int t = 0; t < 2; t++) {
        int idx = tid + t * 256;   // 512 x 16B
        int r = idx >> 2, c = idx & 3;
        cp16(sm + r * ROW_B + c * 16, g + (row0 + r) * (size_t)ld + kb + c * 8);
    }
}

__global__ void __launch_bounds__(256, 1) gemm_mma_kernel(
    const __nv_bfloat16* __restrict__ Ah0, const __nv_bfloat16* __restrict__ Al0,
    int lda0, int nk0,
    const __nv_bfloat16* __restrict__ Ah1, const __nv_bfloat16* __restrict__ Al1,
    int lda1,
    const __nv_bfloat16* __restrict__ Bh, const __nv_bfloat16* __restrict__ Bl,
    int ldb, float* __restrict__ out, int ldo, int nk)
{
    extern __shared__ char smem[];
    uint32_t sb = smem_u32(smem);
    int tid = threadIdx.x, lane = tid & 31, wid = tid >> 5;
    int wm = wid & 1, wn = wid >> 1;
    size_t m0 = (size_t)blockIdx.x * 128;
    int n0 = blockIdx.y * 128;

    float acc[4][4][4];
    #pragma unroll
    for (int a = 0; a < 4; a++)
        #pragma unroll
        for (int b = 0; b < 4; b++)
            #pragma unroll
            for (int c = 0; c < 4; c++) acc[a][b][c] = 0.f;

    // ---- chunk loader ----
    auto load_chunk = [&](int i, int s) {
        uint32_t st = sb + s * STAGE_B;
        const __nv_bfloat16 *ah, *al;
        int lda, kb;
        if (i < nk0) { ah = Ah0; al = Al0; lda = lda0; kb = i * 32; }
        else         { ah = Ah1; al = Al1; lda = lda1; kb = (i - nk0) * 32; }
        load_tile(st,              ah, m0, lda, kb, tid);
        load_tile(st + TILE_B,     al, m0, lda, kb, tid);
        load_tile(st + 2 * TILE_B, Bh, (size_t)n0, ldb, i * 32, tid);
        load_tile(st + 3 * TILE_B, Bl, (size_t)n0, ldb, i * 32, tid);
    };

    load_chunk(0, 0);
    CP_COMMIT();

    for (int i = 0; i < nk; i++) {
        if (i + 1 < nk) { load_chunk(i + 1, (i + 1) & 1); CP_COMMIT(); cp_wait<1>(); }
        else            { cp_wait<0>(); }
        __syncthreads();

        uint32_t st = sb + (i & 1) * STAGE_B;
        #pragma unroll
        for (int kk = 0; kk < 32; kk += 16) {
            uint32_t ah[4][4], al[4][4], bh[2][4], bl[2][4];
            int arow = wm * 64 + (lane & 15);
            int acol = kk + ((lane >> 4) << 3);
            #pragma unroll
            for (int mi = 0; mi < 4; mi++) {
                uint32_t ad = st + (arow + mi * 16) * ROW_B + acol * 2;
                ldsm4(ah[mi], ad);
                ldsm4(al[mi], ad + TILE_B);
            }
            int brow = wn * 32 + ((lane >> 4) << 3) + (lane & 7);
            int bcol = kk + (((lane >> 3) & 1) << 3);
            #pragma unroll
            for (int g = 0; g < 2; g++) {
                uint32_t bd = st + 2 * TILE_B + (brow + g * 16) * ROW_B + bcol * 2;
                ldsm4(bh[g], bd);
                ldsm4(bl[g], bd + TILE_B);
            }
            #pragma unroll
            for (int mi = 0; mi < 4; mi++)
                #pragma unroll
                for (int ni = 0; ni < 4; ni++) {
                    const uint32_t* pbh = &bh[ni >> 1][(ni & 1) * 2];
                    const uint32_t* pbl = &bl[ni >> 1][(ni & 1) * 2];
                    mma_bf16(acc[mi][ni], ah[mi], pbh);  // hh
                    mma_bf16(acc[mi][ni], ah[mi], pbl);  // hl
                    mma_bf16(acc[mi][ni], al[mi], pbh);  // lh
                }
        }
        __syncthreads();
    }

    // ---- epilogue: fp32 stores (float2 pairs land on full 32B sectors) ----
    int r0 = wm * 64 + (lane >> 2);
    int c0 = n0 + wn * 32 + (lane & 3) * 2;
    #pragma unroll
    for (int mi = 0; mi < 4; mi++)
        #pragma unroll
        for (int ni = 0; ni < 4; ni++) {
            size_t row = m0 + r0 + mi * 16;
            int col = c0 + ni * 8;
            *(float2*)(out + row * (size_t)ldo + col)       = make_float2(acc[mi][ni][0], acc[mi][ni][1]);
            *(float2*)(out + (row + 8) * (size_t)ldo + col) = make_float2(acc[mi][ni][2], acc[mi][ni][3]);
        }
}

// ---------------- scan kernels ----------------
__global__ void carry_kernel() {
    int b = blockIdx.x >> 6;
    int c = blockIdx.x & 63;
    int n = threadIdx.x;
    float2 lam = g_lam[n];
    float sre = 0.f, sim = 0.f;
    const float* base = g_S + ((size_t)(b * T + c * CHUNK)) * SCOLS;
    #pragma unroll 4
    for (int j = 0; j < CHUNK; j++) {
        float bre = base[(size_t)j * SCOLS + n];
        float bim = base[(size_t)j * SCOLS + NSTATE + n];
        float nre = fmaf(lam.x, sre, fmaf(-lam.y, sim, bre));
        float nim = fmaf(lam.x, sim, fmaf( lam.y, sre, bim));
        sre = nre; sim = nim;
    }
    size_t idx = (((size_t)b * NC + c) * NSTATE + n) * 2;
    g_carry[idx]     = sre;
    g_carry[idx + 1] = sim;
}

__global__ void combine_kernel() {
    int b = blockIdx.x;
    int n = threadIdx.x;
    double2 lL = g_lamL[n];
    double pre = 0.0, pim = 0.0;
    for (int c = 0; c < NC; c++) {
        size_t idx = (((size_t)b * NC + c) * NSTATE + n) * 2;
        double cre = (double)g_carry[idx];
        double cim = (double)g_carry[idx + 1];
        double nre = lL.x * pre - lL.y * pim + cre;
        double nim = lL.x * pim + lL.y * pre + cim;
        pre = nre; pim = nim;
        g_carry[idx]     = (float)pre;
        g_carry[idx + 1] = (float)pim;
    }
}

__global__ void scan_final_kernel() {
    int b = blockIdx.x >> 6;
    int c = blockIdx.x & 63;
    int n = threadIdx.x;
    float2 lam = g_lam[n];
    float sre = 0.f, sim = 0.f;
    if (c > 0) {
        size_t pidx = (((size_t)b * NC + (c - 1)) * NSTATE + n) * 2;
        sre = g_carry[pidx];
        sim = g_carry[pidx + 1];
    }
    size_t rbase = (size_t)(b * T + c * CHUNK);
    const float* base = g_S + rbase * SCOLS;
    #pragma unroll 2
    for (int j = 0; j < CHUNK; j++) {
        float bre = base[(size_t)j * SCOLS + n];
        float bim = base[(size_t)j * SCOLS + NSTATE + n];
        float nre = fmaf(lam.x, sre, fmaf(-lam.y, sim, bre));
        float nim = fmaf(lam.x, sim, fmaf( lam.y, sre, bim));
        sre = nre; sim = nim;
        size_t orow = (rbase + j) * SCOLS;
        __nv_bfloat16 h, l;
        split_bf16(nre, h, l);
        g_Sh[orow + n] = h; g_Sl[orow + n] = l;
        split_bf16(nim, h, l);
        g_Sh[orow + NSTATE + n] = h; g_Sl[orow + NSTATE + n] = l;
    }
}

// ---------------- launch ----------------
extern "C" void kernel_launch(void* const* d_in, const int* in_sizes, int n_in,
                              void* d_out, int out_size) {
    const float* x         = (const float*)d_in[0];
    const float* nu_log    = (const float*)d_in[1];
    const float* theta_log = (const float*)d_in[2];
    const float* gamma_log = (const float*)d_in[3];
    const float* B_re      = (const float*)d_in[4];
    const float* B_im      = (const float*)d_in[5];
    const float* C_re      = (const float*)d_in[6];
    const float* C_im      = (const float*)d_in[7];
    const float* D         = (const float*)d_in[8];
    float* out = (float*)d_out;

    // resolve device-global addresses for kernel params
    __nv_bfloat16 *xh, *xl, *w1h, *w1l, *sh, *sl, *woh, *wol;
    float* S;
    cudaGetSymbolAddress((void**)&xh,  g_xh);
    cudaGetSymbolAddress((void**)&xl,  g_xl);
    cudaGetSymbolAddress((void**)&w1h, g_W1h);
    cudaGetSymbolAddress((void**)&w1l, g_W1l);
    cudaGetSymbolAddress((void**)&sh,  g_Sh);
    cudaGetSymbolAddress((void**)&sl,  g_Sl);
    cudaGetSymbolAddress((void**)&woh, g_Woh);
    cudaGetSymbolAddress((void**)&wol, g_Wol);
    cudaGetSymbolAddress((void**)&S,   g_S);

    cudaFuncSetAttribute(gemm_mma_kernel, cudaFuncAttributeMaxDynamicSharedMemorySize, GSMEM);

    prep_lambda_kernel<<<1, 256>>>(nu_log, theta_log);
    prep_w1_kernel<<<(SCOLS * IN_F + 255) / 256, 256>>>(gamma_log, B_re, B_im);
    prep_wout_kernel<<<(OUT_F * KOUT + 255) / 256, 256>>>(C_re, C_im, D);
    convert_x_kernel<<<(MROWS * IN_F / 4) / 256, 256>>>(x);

    // GEMM1: Bu = x @ W1^T   [65536 x 512], K=128
    gemm_mma_kernel<<<dim3(MROWS / 128, SCOLS / 128), 256, GSMEM>>>(
        xh, xl, IN_F, 4, xh, xl, IN_F, w1h, w1l, IN_F, S, SCOLS, 4);

    carry_kernel<<<BATCH * NC, NSTATE>>>();
    combine_kernel<<<BATCH, NSTATE>>>();
    scan_final_kernel<<<BATCH * NC, NSTATE>>>();

    // GEMM2: out = S @ Wout^T (K 0..512 from states, 512..640 from x)
    gemm_mma_kernel<<<dim3(MROWS / 128, 1), 256, GSMEM>>>(
        sh, sl, SCOLS, 16, xh, xl, IN_F, woh, wol, KOUT, out, OUT_F, 20);
}